// round 14
// baseline (speedup 1.0000x reference)
#include <cuda_runtime.h>

// PointAttentionEncoder1D — 2 threads/point (16 ch each), f32x2 packed.
// MLPs single-path (register-lean); ONLY the weight_process loop is dualized
// across a neighbor pair so its weight LDS (the dominant smem traffic) is
// amortized 2x. Peak live ~160 regs -> (128,3) cap 168, no spills.

typedef unsigned long long u64;
constexpr int KNB = 16;

__device__ __forceinline__ u64 pack2(float lo, float hi) {
    u64 r; asm("mov.b64 %0, {%1,%2};" : "=l"(r) : "f"(lo), "f"(hi)); return r;
}
__device__ __forceinline__ void unpack2(u64 v, float& lo, float& hi) {
    asm("mov.b64 {%0,%1}, %2;" : "=f"(lo), "=f"(hi) : "l"(v));
}
__device__ __forceinline__ u64 fma2(u64 a, u64 b, u64 c) {
    u64 d; asm("fma.rn.f32x2 %0, %1, %2, %3;" : "=l"(d) : "l"(a), "l"(b), "l"(c)); return d;
}
__device__ __forceinline__ u64 add2(u64 a, u64 b) {
    u64 d; asm("add.rn.f32x2 %0, %1, %2;" : "=l"(d) : "l"(a), "l"(b)); return d;
}
__device__ __forceinline__ u64 neg2(u64 a) { return a ^ 0x8000000080000000ULL; }
__device__ __forceinline__ float leaky(float v) { return fmaxf(v, 0.01f * v); }

// MLP 3 -> 16 (leaky) -> 32, this thread's 16-channel half.
__device__ __forceinline__ void mlp_half(
    const float* __restrict__ w1, const float* __restrict__ b1,
    const float* __restrict__ w2h, const float* __restrict__ b2h,
    float x0, float x1, float x2, u64* __restrict__ o)
{
    const u64 X0 = pack2(x0, x0), X1 = pack2(x1, x1), X2 = pack2(x2, x2);
    float h[16];
#pragma unroll
    for (int i = 0; i < 8; i++) {
        u64 a = *(const u64*)(b1 + 2 * i);
        a = fma2(X0, *(const u64*)(w1 + 2 * i),      a);
        a = fma2(X1, *(const u64*)(w1 + 16 + 2 * i), a);
        a = fma2(X2, *(const u64*)(w1 + 32 + 2 * i), a);
        float va, vb; unpack2(a, va, vb);
        h[2 * i] = leaky(va); h[2 * i + 1] = leaky(vb);
    }
    const ulonglong2* bb = (const ulonglong2*)b2h;
#pragma unroll
    for (int c = 0; c < 4; c++) { ulonglong2 t = bb[c]; o[2*c] = t.x; o[2*c+1] = t.y; }
#pragma unroll
    for (int i = 0; i < 16; i++) {
        const u64 h2 = pack2(h[i], h[i]);
        const ulonglong2* w2r = (const ulonglong2*)(w2h + i * 32);
#pragma unroll
        for (int c = 0; c < 4; c++) {
            ulonglong2 t = w2r[c];
            o[2*c]   = fma2(h2, t.x, o[2*c]);
            o[2*c+1] = fma2(h2, t.y, o[2*c+1]);
        }
    }
}

__global__ void __launch_bounds__(128, 3)
pae_kernel(const float* __restrict__ center,   // [P,1,3]
           const float* __restrict__ other,    // [P,K,3]
           const float* __restrict__ mw1,      // [6,3,16]
           const float* __restrict__ mb1,      // [6,16]
           const float* __restrict__ mw2,      // [6,16,32]
           const float* __restrict__ mb2,      // [6,32]
           const float* __restrict__ ww1,      // [32,64]
           const float* __restrict__ wb1,      // [64]
           const float* __restrict__ ww2,      // [64,32]
           const float* __restrict__ wb2,      // [32]
           float* __restrict__ out,            // [P,32]
           int P)
{
    __shared__ __align__(16) float s_mw1[6 * 48];
    __shared__ __align__(16) float s_mb1[6 * 16];
    __shared__ __align__(16) float s_mw2[6 * 512];
    __shared__ __align__(16) float s_mb2[6 * 32];
    __shared__ __align__(16) float s_w1t[64 * 32];   // wp_w1 transposed: [m][c]
    __shared__ __align__(16) float s_wb1[64];
    __shared__ __align__(16) float s_w2[64 * 32];    // wp_w2: [m][c]
    __shared__ __align__(16) float s_wb2[32];

    const int tid = threadIdx.x;
    const int nt  = blockDim.x;
    for (int i = tid; i < 6 * 48;  i += nt) s_mw1[i] = mw1[i];
    for (int i = tid; i < 6 * 16;  i += nt) s_mb1[i] = mb1[i];
    for (int i = tid; i < 6 * 512; i += nt) s_mw2[i] = mw2[i];
    for (int i = tid; i < 6 * 32;  i += nt) s_mb2[i] = mb2[i];
    for (int i = tid; i < 32 * 64; i += nt) {
        int c = i >> 6, m = i & 63;
        s_w1t[m * 32 + c] = ww1[i];
    }
    for (int i = tid; i < 64;      i += nt) s_wb1[i] = wb1[i];
    for (int i = tid; i < 64 * 32; i += nt) s_w2[i] = ww2[i];
    for (int i = tid; i < 32;      i += nt) s_wb2[i] = wb2[i];
    __syncthreads();

    const int g = blockIdx.x * nt + tid;
    if (g >= 2 * P) return;
    const int p    = g >> 1;
    const int half = g & 1;
    const int co   = 16 * half;

    const float cx = center[p * 3 + 0];
    const float cy = center[p * 3 + 1];
    const float cz = center[p * 3 + 2];

    u64 q2[8];
    mlp_half(s_mw1, s_mb1, s_mw2 + co, s_mb2 + co, cx, cy, cz, q2);

    u64 acc2[8];
#pragma unroll
    for (int c = 0; c < 8; c++) acc2[c] = 0ULL;

    // ================= j = 0 : center-as-neighbor (single path) =================
    {
        u64 pos2[8];
        mlp_half(s_mw1 + 5*48, s_mb1 + 5*16, s_mw2 + 5*512 + co, s_mb2 + 5*32 + co,
                 0.f, 0.f, 0.f, pos2);
        u64 u2[8];
        mlp_half(s_mw1 + 1*48, s_mb1 + 1*16, s_mw2 + 1*512 + co, s_mb2 + 1*32 + co,
                 cx, cy, cz, u2);
#pragma unroll
        for (int c = 0; c < 8; c++)
            u2[c] = add2(add2(q2[c], pos2[c]), neg2(u2[c]));

        u64 wacc[8];
        {
            const ulonglong2* bb = (const ulonglong2*)(s_wb2 + co);
#pragma unroll
            for (int c = 0; c < 4; c++) { ulonglong2 t = bb[c]; wacc[2*c] = t.x; wacc[2*c+1] = t.y; }
        }
#pragma unroll 2
        for (int m = 0; m < 64; m++) {
            const ulonglong2* w1r = (const ulonglong2*)(s_w1t + m * 32 + co);
            u64 s0 = 0ULL, s1 = 0ULL;
#pragma unroll
            for (int c = 0; c < 4; c++) {
                ulonglong2 t = w1r[c];
                s0 = fma2(u2[2*c],   t.x, s0);
                s1 = fma2(u2[2*c+1], t.y, s1);
            }
            s0 = add2(s0, s1);
            float pa, pb; unpack2(s0, pa, pb);
            float part = pa + pb;
            part += __shfl_xor_sync(0xffffffffu, part, 1);
            float hh = leaky(part + s_wb1[m]);
            const u64 h2 = pack2(hh, hh);
            const ulonglong2* w2r = (const ulonglong2*)(s_w2 + m * 32 + co);
#pragma unroll
            for (int c = 0; c < 4; c++) {
                ulonglong2 t = w2r[c];
                wacc[2*c]   = fma2(h2, t.x, wacc[2*c]);
                wacc[2*c+1] = fma2(h2, t.y, wacc[2*c+1]);
            }
        }

        float wf[16];
#pragma unroll
        for (int c = 0; c < 8; c++) unpack2(wacc[c], wf[2*c], wf[2*c+1]);
        float mx = wf[0];
#pragma unroll
        for (int c = 1; c < 16; c++) mx = fmaxf(mx, wf[c]);
        mx = fmaxf(mx, __shfl_xor_sync(0xffffffffu, mx, 1));
        float ssum = 0.f;
#pragma unroll
        for (int c = 0; c < 16; c++) { float e = __expf(wf[c] - mx); wf[c] = e; ssum += e; }
        ssum += __shfl_xor_sync(0xffffffffu, ssum, 1);
        const float inv = __frcp_rn(ssum);

        u64 e2[8];
#pragma unroll
        for (int c = 0; c < 8; c++) e2[c] = pack2(wf[2*c] * inv, wf[2*c+1] * inv);
#pragma unroll
        for (int c = 0; c < 8; c++) acc2[c] = fma2(e2[c], pos2[c], acc2[c]);

        u64 vt[8];
        mlp_half(s_mw1 + 2*48, s_mb1 + 2*16, s_mw2 + 2*512 + co, s_mb2 + 2*32 + co,
                 cx, cy, cz, vt);
#pragma unroll
        for (int c = 0; c < 8; c++) acc2[c] = fma2(e2[c], vt[c], acc2[c]);
    }

    // ===== neighbor pairs: MLPs single-path, WP loop dualized (weights shared) =====
    const float* onb = other + p * KNB * 3;
#pragma unroll 1
    for (int t = 0; t < KNB / 2; t++) {
        const float* na = onb + 6 * t;
        const float a0 = na[0], a1 = na[1], a2 = na[2];
        const float b0 = na[3], b1v = na[4], b2v = na[5];

        // row A: pos_a, u_a
        u64 pa[8];
        mlp_half(s_mw1 + 5*48, s_mb1 + 5*16, s_mw2 + 5*512 + co, s_mb2 + 5*32 + co,
                 cx - a0, cy - a1, cz - a2, pa);
        u64 ua[8];
        mlp_half(s_mw1 + 3*48, s_mb1 + 3*16, s_mw2 + 3*512 + co, s_mb2 + 3*32 + co,
                 a0, a1, a2, ua);
#pragma unroll
        for (int c = 0; c < 8; c++)
            ua[c] = add2(add2(q2[c], pa[c]), neg2(ua[c]));

        // row B: pos_b, u_b
        u64 pb[8];
        mlp_half(s_mw1 + 5*48, s_mb1 + 5*16, s_mw2 + 5*512 + co, s_mb2 + 5*32 + co,
                 cx - b0, cy - b1v, cz - b2v, pb);
        u64 ub[8];
        mlp_half(s_mw1 + 3*48, s_mb1 + 3*16, s_mw2 + 3*512 + co, s_mb2 + 3*32 + co,
                 b0, b1v, b2v, ub);
#pragma unroll
        for (int c = 0; c < 8; c++)
            ub[c] = add2(add2(q2[c], pb[c]), neg2(ub[c]));

        // dual WP: each weight row loaded ONCE, applied to both u_a and u_b
        u64 wa[8], wb_[8];
        {
            const ulonglong2* bb = (const ulonglong2*)(s_wb2 + co);
#pragma unroll
            for (int c = 0; c < 4; c++) {
                ulonglong2 v = bb[c];
                wa[2*c] = v.x;  wa[2*c+1] = v.y;
                wb_[2*c] = v.x; wb_[2*c+1] = v.y;
            }
        }
#pragma unroll 1
        for (int m = 0; m < 64; m++) {
            const ulonglong2* w1r = (const ulonglong2*)(s_w1t + m * 32 + co);
            u64 sa0 = 0ULL, sa1 = 0ULL, sb0 = 0ULL, sb1 = 0ULL;
#pragma unroll
            for (int c = 0; c < 4; c++) {
                ulonglong2 v = w1r[c];
                sa0 = fma2(ua[2*c],   v.x, sa0);
                sa1 = fma2(ua[2*c+1], v.y, sa1);
                sb0 = fma2(ub[2*c],   v.x, sb0);
                sb1 = fma2(ub[2*c+1], v.y, sb1);
            }
            sa0 = add2(sa0, sa1); sb0 = add2(sb0, sb1);
            float xa, ya; unpack2(sa0, xa, ya);
            float xb, yb; unpack2(sb0, xb, yb);
            float parta = xa + ya, partb = xb + yb;
            parta += __shfl_xor_sync(0xffffffffu, parta, 1);
            partb += __shfl_xor_sync(0xffffffffu, partb, 1);
            const float bm = s_wb1[m];
            const float hha = leaky(parta + bm);
            const float hhb = leaky(partb + bm);
            const u64 h2a = pack2(hha, hha);
            const u64 h2b = pack2(hhb, hhb);
            const ulonglong2* w2r = (const ulonglong2*)(s_w2 + m * 32 + co);
#pragma unroll
            for (int c = 0; c < 4; c++) {
                ulonglong2 v = w2r[c];
                wa[2*c]    = fma2(h2a, v.x, wa[2*c]);
                wa[2*c+1]  = fma2(h2a, v.y, wa[2*c+1]);
                wb_[2*c]   = fma2(h2b, v.x, wb_[2*c]);
                wb_[2*c+1] = fma2(h2b, v.y, wb_[2*c+1]);
            }
        }

        // dual softmax (overwrites wa/wb_ register space)
        float wfa[16], wfb[16];
#pragma unroll
        for (int c = 0; c < 8; c++) { unpack2(wa[c], wfa[2*c], wfa[2*c+1]); unpack2(wb_[c], wfb[2*c], wfb[2*c+1]); }
        float mxa = wfa[0], mxb = wfb[0];
#pragma unroll
        for (int c = 1; c < 16; c++) { mxa = fmaxf(mxa, wfa[c]); mxb = fmaxf(mxb, wfb[c]); }
        mxa = fmaxf(mxa, __shfl_xor_sync(0xffffffffu, mxa, 1));
        mxb = fmaxf(mxb, __shfl_xor_sync(0xffffffffu, mxb, 1));
        float sa = 0.f, sb = 0.f;
#pragma unroll
        for (int c = 0; c < 16; c++) {
            float ea = __expf(wfa[c] - mxa); wfa[c] = ea; sa += ea;
            float eb = __expf(wfb[c] - mxb); wfb[c] = eb; sb += eb;
        }
        sa += __shfl_xor_sync(0xffffffffu, sa, 1);
        sb += __shfl_xor_sync(0xffffffffu, sb, 1);
        const float inva = __frcp_rn(sa);
        const float invb = __frcp_rn(sb);

        u64 ea2[8], eb2[8];
#pragma unroll
        for (int c = 0; c < 8; c++) {
            ea2[c] = pack2(wfa[2*c] * inva, wfa[2*c+1] * inva);
            eb2[c] = pack2(wfb[2*c] * invb, wfb[2*c+1] * invb);
        }

        // acc += e*pos  (retires pos_a/pos_b before v-MLPs)
#pragma unroll
        for (int c = 0; c < 8; c++) {
            acc2[c] = fma2(ea2[c], pa[c], acc2[c]);
            acc2[c] = fma2(eb2[c], pb[c], acc2[c]);
        }

        // v-MLPs sequential in freed registers
        u64 vt[8];
        mlp_half(s_mw1 + 4*48, s_mb1 + 4*16, s_mw2 + 4*512 + co, s_mb2 + 4*32 + co,
                 a0, a1, a2, vt);
#pragma unroll
        for (int c = 0; c < 8; c++) acc2[c] = fma2(ea2[c], vt[c], acc2[c]);
        mlp_half(s_mw1 + 4*48, s_mb1 + 4*16, s_mw2 + 4*512 + co, s_mb2 + 4*32 + co,
                 b0, b1v, b2v, vt);
#pragma unroll
        for (int c = 0; c < 8; c++) acc2[c] = fma2(eb2[c], vt[c], acc2[c]);
    }

    // store this half's 16 floats, coalesced across the pair
    ulonglong2* op = (ulonglong2*)(out + p * 32 + co);
#pragma unroll
    for (int c = 0; c < 4; c++) {
        ulonglong2 t; t.x = acc2[2*c]; t.y = acc2[2*c+1];
        op[c] = t;
    }
}

extern "C" void kernel_launch(void* const* d_in, const int* in_sizes, int n_in,
                              void* d_out, int out_size)
{
    const float* center = (const float*)d_in[0];
    const float* other  = (const float*)d_in[1];
    const float* mw1    = (const float*)d_in[2];
    const float* mb1    = (const float*)d_in[3];
    const float* mw2    = (const float*)d_in[4];
    const float* mb2    = (const float*)d_in[5];
    const float* ww1    = (const float*)d_in[6];
    const float* wb1    = (const float*)d_in[7];
    const float* ww2    = (const float*)d_in[8];
    const float* wb2    = (const float*)d_in[9];
    float* out = (float*)d_out;

    const int P = in_sizes[0] / 3;
    const int block = 128;
    const int grid = (2 * P + block - 1) / block;
    pae_kernel<<<grid, block>>>(center, other, mw1, mb1, mw2, mb2,
                                ww1, wb1, ww2, wb2, out, P);
}